// round 7
// baseline (speedup 1.0000x reference)
#include <cuda_runtime.h>
#include <cuda_bf16.h>

// Problem constants
#define BB    16
#define MM    127
#define PP    3
#define KLEN  132
#define NSPAN 126
#define SS    256
#define CDIM  3
#define EPSF  1e-8f

#define EVT 128      // threads per block
#define GPB 4        // iu values per block

// ---------------------------------------------------------------------------
// Warp-collective knot prep: lanes 0..31 cooperatively cumsum KLEN=132 knots
// (5 per lane), shuffle-scan the lane totals, normalize in-warp (k0 from
// lane 0, total from lane 31 via shuffle), and store the normalized knot
// vector to sK. Numerics identical to the proven R5 prep.
// ---------------------------------------------------------------------------
__device__ __forceinline__ void scan_knots_warp(const float* __restrict__ knots,
                                                float* __restrict__ sK,
                                                int lane)
{
    float vals[5];
    float run = 0.f;
    #pragma unroll
    for (int k = 0; k < 5; k++) {
        const int idx = lane * 5 + k;
        if (idx < KLEN) {
            float w = knots[idx];
            run += (w < 0.f) ? 1e-4f : w;
            vals[k] = run;
        }
    }
    float tot = run;
    #pragma unroll
    for (int off = 1; off < 32; off <<= 1) {
        float n = __shfl_up_sync(0xFFFFFFFFu, tot, off);
        if (lane >= off) tot += n;
    }
    const float pre = tot - run;                       // exclusive prefix
    const float k0   = __shfl_sync(0xFFFFFFFFu, vals[0] /* +pre(=0) */, 0);
    const float kend = __shfl_sync(0xFFFFFFFFu, tot, 31);  // full cumsum
    const float inv  = 1.f / (kend - k0);
    #pragma unroll
    for (int k = 0; k < 5; k++) {
        const int idx = lane * 5 + k;
        if (idx < KLEN) sK[idx] = (vals[k] + pre - k0) * inv;
    }
}

// ---------------------------------------------------------------------------
// Span (binary search over monotone predicate, == reference masked-argmin)
// + cubic Cox-de-Boor basis with the reference's exact FP expression order.
// ---------------------------------------------------------------------------
__device__ __forceinline__ void span_basis(const float* __restrict__ sK,
                                           float t, int* span_out, float4* n_out)
{
    int lo = -1, hi = NSPAN;
    while (hi - lo > 1) {
        const int mid = (lo + hi) >> 1;
        if (t - sK[3 + mid] > EPSF) lo = mid; else hi = mid;
    }
    int idx = (lo < 0) ? 0 : lo;
    int span = idx + PP;
    span = (span < PP) ? PP : (span > MM ? MM : span);

    float Ni[4];
    Ni[0] = 1.f; Ni[1] = 0.f; Ni[2] = 0.f; Ni[3] = 0.f;
    #pragma unroll
    for (int k = 1; k <= PP; k++) {
        float saved = 0.f;
        #pragma unroll
        for (int r = 0; r < 3; r++) {
            if (r >= k) break;
            const float K1 = sK[span + r + 1];
            const float K2 = sK[span + 1 - k + r];
            const float denom = (K1 - t) + (t - K2);   // exact ref order
            const float temp  = (denom == 0.f) ? 1e-4f : Ni[r] / denom;
            Ni[r] = saved + (K1 - t) * temp;
            saved = (t - K2) * temp;
        }
        Ni[k] = saved;
    }
    *span_out = span;
    *n_out = make_float4(Ni[0], Ni[1], Ni[2], Ni[3]);
}

// ---------------------------------------------------------------------------
// Fused kernel: one 128-thread block per (b, group of 4 consecutive iu).
//  A) warp 0 scans u-knots, warp 1 scans v-knots (others idle briefly)
//  B) threads 0..3 compute the block's 4 u-bases -> smem;
//     every thread computes its own two v-bases -> registers
//  C) software-pipelined eval loop (proven R5 structure): stage-1 LDGs for
//     iu_{g+1} issued before iu_g's barrier; double-buffered sT; scalar-LDS
//     stage 2 (conflict-free: lane stride 12B, gcd(3,32)=1).
// ---------------------------------------------------------------------------
__global__ __launch_bounds__(EVT) void fused_kernel(
    const float* __restrict__ ctrl,
    const float* __restrict__ knot_u,
    const float* __restrict__ knot_v,
    const float* __restrict__ uu,
    const float* __restrict__ vv,
    float* __restrict__ out)
{
    const int bid = blockIdx.x;             // 0 .. 1023
    const int b   = bid >> 6;
    const int iug = (bid & 63) * GPB;
    const int tid = threadIdx.x;
    const int wid = tid >> 5;
    const int lane = tid & 31;

    __shared__ float  sKu[KLEN];
    __shared__ float  sKv[KLEN];
    __shared__ float4 s_nu[GPB];
    __shared__ int    s_us[GPB];
    __shared__ float  sT[2][128 * CDIM];    // double-buffered u-contracted row

    // A) knot scans
    if (wid == 0)      scan_knots_warp(knot_u + b * KLEN, sKu, lane);
    else if (wid == 1) scan_knots_warp(knot_v + b * KLEN, sKv, lane);
    __syncthreads();

    // B) bases
    if (tid < GPB) {
        int us; float4 nu;
        span_basis(sKu, uu[iug + tid], &us, &nu);
        s_nu[tid] = nu;
        s_us[tid] = us;
    }
    const int iv0 = tid, iv1 = tid + EVT;
    int vs0, vs1; float4 nv0, nv1;
    span_basis(sKv, vv[iv0], &vs0, &nv0);
    span_basis(sKv, vv[iv1], &vs1, &nv1);
    const int voff0 = (vs0 - 3) * CDIM;
    const int voff1 = (vs1 - 3) * CDIM;
    __syncthreads();

    // C) pipelined eval
    float4 r0, r1, r2, r3;
    if (tid < 96) {
        const float4* cb4 = (const float4*)(ctrl + (size_t)(b * 128 + (s_us[0] - 3)) * 384);
        r0 = cb4[tid]; r1 = cb4[tid + 96]; r2 = cb4[tid + 192]; r3 = cb4[tid + 288];
    }

    #pragma unroll
    for (int g = 0; g < GPB; g++) {
        const int p = g & 1;

        if (tid < 96) {
            const float4 q = s_nu[g];
            float4 acc;
            acc.x = q.x * r0.x + q.y * r1.x + q.z * r2.x + q.w * r3.x;
            acc.y = q.x * r0.y + q.y * r1.y + q.z * r2.y + q.w * r3.y;
            acc.z = q.x * r0.z + q.y * r1.z + q.z * r2.z + q.w * r3.z;
            acc.w = q.x * r0.w + q.y * r1.w + q.z * r2.w + q.w * r3.w;
            ((float4*)sT[p])[tid] = acc;

            if (g + 1 < GPB) {   // issue next loads before the barrier
                const float4* cb4 = (const float4*)(ctrl + (size_t)(b * 128 + (s_us[g + 1] - 3)) * 384);
                r0 = cb4[tid]; r1 = cb4[tid + 96]; r2 = cb4[tid + 192]; r3 = cb4[tid + 288];
            }
        }
        __syncthreads();

        const float* t0 = sT[p] + voff0;
        const float* t1 = sT[p] + voff1;
        const size_t obase = (((size_t)b * SS + (iug + g)) * SS) * CDIM;
        {
            const float ax = nv0.x * t0[0] + nv0.y * t0[3] + nv0.z * t0[6] + nv0.w * t0[9];
            const float ay = nv0.x * t0[1] + nv0.y * t0[4] + nv0.z * t0[7] + nv0.w * t0[10];
            const float az = nv0.x * t0[2] + nv0.y * t0[5] + nv0.z * t0[8] + nv0.w * t0[11];
            const size_t o = obase + (size_t)iv0 * CDIM;
            out[o] = ax; out[o + 1] = ay; out[o + 2] = az;
        }
        {
            const float ax = nv1.x * t1[0] + nv1.y * t1[3] + nv1.z * t1[6] + nv1.w * t1[9];
            const float ay = nv1.x * t1[1] + nv1.y * t1[4] + nv1.z * t1[7] + nv1.w * t1[10];
            const float az = nv1.x * t1[2] + nv1.y * t1[5] + nv1.z * t1[8] + nv1.w * t1[11];
            const size_t o = obase + (size_t)iv1 * CDIM;
            out[o] = ax; out[o + 1] = ay; out[o + 2] = az;
        }
        // No second barrier: double buffer + next iteration's barrier covers WAR.
    }
}

// ---------------------------------------------------------------------------
// Inputs (metadata order): ctrl_pts, knot_u, knot_v, u, v. Output: float32.
// ---------------------------------------------------------------------------
extern "C" void kernel_launch(void* const* d_in, const int* in_sizes, int n_in,
                              void* d_out, int out_size)
{
    const float* ctrl   = (const float*)d_in[0];
    const float* knot_u = (const float*)d_in[1];
    const float* knot_v = (const float*)d_in[2];
    const float* uu     = (const float*)d_in[3];
    const float* vv     = (const float*)d_in[4];
    float* out = (float*)d_out;

    fused_kernel<<<BB * SS / GPB, EVT>>>(ctrl, knot_u, knot_v, uu, vv, out);
}

// round 8
// speedup vs baseline: 1.1935x; 1.1935x over previous
#include <cuda_runtime.h>
#include <cuda_bf16.h>

// Problem constants
#define BB    16
#define MM    127
#define PP    3
#define KLEN  132
#define NSPAN 126
#define SS    256
#define CDIM  3
#define EPSF  1e-8f

#define EVT 256      // threads per block (one iv per thread)
#define GPB 8        // iu values per block

// ---------------------------------------------------------------------------
// Warp-collective knot prep: lanes 0..31 cumsum KLEN=132 knots (5/lane),
// shuffle-scan lane totals, normalize in-warp, store normalized knots to sK.
// Numerics identical to the proven R5 prep.
// ---------------------------------------------------------------------------
__device__ __forceinline__ void scan_knots_warp(const float* __restrict__ knots,
                                                float* __restrict__ sK,
                                                int lane)
{
    float vals[5];
    float run = 0.f;
    #pragma unroll
    for (int k = 0; k < 5; k++) {
        const int idx = lane * 5 + k;
        if (idx < KLEN) {
            float w = knots[idx];
            run += (w < 0.f) ? 1e-4f : w;
            vals[k] = run;
        }
    }
    float tot = run;
    #pragma unroll
    for (int off = 1; off < 32; off <<= 1) {
        float n = __shfl_up_sync(0xFFFFFFFFu, tot, off);
        if (lane >= off) tot += n;
    }
    const float pre = tot - run;                           // exclusive prefix
    const float k0   = __shfl_sync(0xFFFFFFFFu, vals[0], 0);
    const float kend = __shfl_sync(0xFFFFFFFFu, tot, 31);  // full cumsum
    const float inv  = 1.f / (kend - k0);
    #pragma unroll
    for (int k = 0; k < 5; k++) {
        const int idx = lane * 5 + k;
        if (idx < KLEN) sK[idx] = (vals[k] + pre - k0) * inv;
    }
}

// ---------------------------------------------------------------------------
// Span (binary search over monotone predicate == reference masked-argmin)
// + cubic Cox-de-Boor basis, reference's exact FP expression order.
// ---------------------------------------------------------------------------
__device__ __forceinline__ void span_basis(const float* __restrict__ sK,
                                           float t, int* span_out, float4* n_out)
{
    int lo = -1, hi = NSPAN;
    while (hi - lo > 1) {
        const int mid = (lo + hi) >> 1;
        if (t - sK[3 + mid] > EPSF) lo = mid; else hi = mid;
    }
    int idx = (lo < 0) ? 0 : lo;
    int span = idx + PP;
    span = (span < PP) ? PP : (span > MM ? MM : span);

    float Ni[4];
    Ni[0] = 1.f; Ni[1] = 0.f; Ni[2] = 0.f; Ni[3] = 0.f;
    #pragma unroll
    for (int k = 1; k <= PP; k++) {
        float saved = 0.f;
        #pragma unroll
        for (int r = 0; r < 3; r++) {
            if (r >= k) break;
            const float K1 = sK[span + r + 1];
            const float K2 = sK[span + 1 - k + r];
            const float denom = (K1 - t) + (t - K2);   // exact ref order
            const float temp  = (denom == 0.f) ? 1e-4f : Ni[r] / denom;
            Ni[r] = saved + (K1 - t) * temp;
            saved = (t - K2) * temp;
        }
        Ni[k] = saved;
    }
    *span_out = span;
    *n_out = make_float4(Ni[0], Ni[1], Ni[2], Ni[3]);
}

// ---------------------------------------------------------------------------
// Fused kernel: one 256-thread block per (b, group of 8 consecutive iu).
//  A) warp 0 scans u-knots, warp 1 scans v-knots (concurrent)
//  B) threads 0..7 compute the block's 8 u-bases -> smem;
//     every thread computes ONE v-basis (iv = tid) -> registers
//  C) software-pipelined eval loop: stage-1 LDGs for iu_{g+1} issued before
//     iu_g's barrier; double-buffered sT; scalar-LDS stage 2 (lane stride
//     12B, conflict-free).
// ---------------------------------------------------------------------------
__global__ __launch_bounds__(EVT) void fused_kernel(
    const float* __restrict__ ctrl,
    const float* __restrict__ knot_u,
    const float* __restrict__ knot_v,
    const float* __restrict__ uu,
    const float* __restrict__ vv,
    float* __restrict__ out)
{
    const int bid = blockIdx.x;             // 0 .. 511
    const int b   = bid >> 5;               // 32 blocks per batch
    const int iug = (bid & 31) * GPB;
    const int tid = threadIdx.x;
    const int wid = tid >> 5;
    const int lane = tid & 31;

    __shared__ float  sKu[KLEN];
    __shared__ float  sKv[KLEN];
    __shared__ float4 s_nu[GPB];
    __shared__ int    s_us[GPB];
    __shared__ float  sT[2][128 * CDIM];    // double-buffered u-contracted row

    // A) knot scans (two warps in parallel)
    if (wid == 0)      scan_knots_warp(knot_u + b * KLEN, sKu, lane);
    else if (wid == 1) scan_knots_warp(knot_v + b * KLEN, sKv, lane);
    __syncthreads();

    // B) bases: 8 u-bases by threads 0..7; one v-basis per thread
    if (tid < GPB) {
        int us; float4 nu;
        span_basis(sKu, uu[iug + tid], &us, &nu);
        s_nu[tid] = nu;
        s_us[tid] = us;
    }
    int vs; float4 nv;
    span_basis(sKv, vv[tid], &vs, &nv);
    const int voff = (vs - 3) * CDIM;
    __syncthreads();

    // C) pipelined eval
    float4 r0, r1, r2, r3;
    if (tid < 96) {
        const float4* cb4 = (const float4*)(ctrl + (size_t)(b * 128 + (s_us[0] - 3)) * 384);
        r0 = cb4[tid]; r1 = cb4[tid + 96]; r2 = cb4[tid + 192]; r3 = cb4[tid + 288];
    }

    #pragma unroll
    for (int g = 0; g < GPB; g++) {
        const int p = g & 1;

        if (tid < 96) {
            const float4 q = s_nu[g];
            float4 acc;
            acc.x = q.x * r0.x + q.y * r1.x + q.z * r2.x + q.w * r3.x;
            acc.y = q.x * r0.y + q.y * r1.y + q.z * r2.y + q.w * r3.y;
            acc.z = q.x * r0.z + q.y * r1.z + q.z * r2.z + q.w * r3.z;
            acc.w = q.x * r0.w + q.y * r1.w + q.z * r2.w + q.w * r3.w;
            ((float4*)sT[p])[tid] = acc;

            if (g + 1 < GPB) {   // issue next loads before the barrier
                const float4* cb4 = (const float4*)(ctrl + (size_t)(b * 128 + (s_us[g + 1] - 3)) * 384);
                r0 = cb4[tid]; r1 = cb4[tid + 96]; r2 = cb4[tid + 192]; r3 = cb4[tid + 288];
            }
        }
        __syncthreads();

        // Stage 2: one point per thread
        const float* t0 = sT[p] + voff;
        const float ax = nv.x * t0[0] + nv.y * t0[3] + nv.z * t0[6] + nv.w * t0[9];
        const float ay = nv.x * t0[1] + nv.y * t0[4] + nv.z * t0[7] + nv.w * t0[10];
        const float az = nv.x * t0[2] + nv.y * t0[5] + nv.z * t0[8] + nv.w * t0[11];
        const size_t o = (((size_t)b * SS + (iug + g)) * SS + tid) * CDIM;
        out[o] = ax; out[o + 1] = ay; out[o + 2] = az;
        // No second barrier: double buffer + next iteration's barrier covers WAR.
    }
}

// ---------------------------------------------------------------------------
// Inputs (metadata order): ctrl_pts, knot_u, knot_v, u, v. Output: float32.
// ---------------------------------------------------------------------------
extern "C" void kernel_launch(void* const* d_in, const int* in_sizes, int n_in,
                              void* d_out, int out_size)
{
    const float* ctrl   = (const float*)d_in[0];
    const float* knot_u = (const float*)d_in[1];
    const float* knot_v = (const float*)d_in[2];
    const float* uu     = (const float*)d_in[3];
    const float* vv     = (const float*)d_in[4];
    float* out = (float*)d_out;

    fused_kernel<<<BB * SS / GPB, EVT>>>(ctrl, knot_u, knot_v, uu, vv, out);
}